// round 13
// baseline (speedup 1.0000x reference)
#include <cuda_runtime.h>
#include <cuda_bf16.h>
#include <cstdint>

#define DIMN 512
#define MT   64
#define NROWS 65536
#define NCTAS (NROWS / MT)        // 1024
#define NTHREADS 1024
#define ETA   0.1f
#define OMETA 0.9f
#define NCH_TOTAL (9 * 8)         // 72 chunks of 64 k-rows

// smem: a-tile [64][512] bf16 swizzled (64KB) + 2 G chunk buffers (64KB each) + flags
static constexpr uint32_t A_OFF   = 0;
static constexpr uint32_t G_OFF0  = 65536;
static constexpr uint32_t G_OFF1  = 131072;
static constexpr uint32_t FL_OFF  = 196608;       // flags[2][8]
static constexpr uint32_t SMEM_TOTAL = 196672;

// G' = -eta * (0.5*(G+G^T)) with zero diagonal, bf16, row-major [K=512][N=512]
__device__ __nv_bfloat16 g_gp[DIMN * DIMN];

__global__ void lca_prep_kernel(const float* __restrict__ G) {
    int idx = blockIdx.x * blockDim.x + threadIdx.x;
    int i = idx >> 9, j = idx & 511;
    float v = (i == j) ? 0.0f : -ETA * 0.5f * (G[idx] + G[j * DIMN + i]);
    g_gp[idx] = __float2bfloat16(v);
}

__device__ __forceinline__ uint32_t smem_u32(const void* p) {
    uint32_t a;
    asm("{ .reg .u64 t; cvta.to.shared.u64 t, %1; cvt.u32.u64 %0, t; }" : "=r"(a) : "l"(p));
    return a;
}
__device__ __forceinline__ void ldsm4(uint32_t* r, uint32_t addr) {
    asm volatile("ldmatrix.sync.aligned.m8n8.x4.shared.b16 {%0,%1,%2,%3}, [%4];"
                 : "=r"(r[0]), "=r"(r[1]), "=r"(r[2]), "=r"(r[3]) : "r"(addr));
}
__device__ __forceinline__ void ldsm4t(uint32_t* r, uint32_t addr) {
    asm volatile("ldmatrix.sync.aligned.m8n8.x4.trans.shared.b16 {%0,%1,%2,%3}, [%4];"
                 : "=r"(r[0]), "=r"(r[1]), "=r"(r[2]), "=r"(r[3]) : "r"(addr));
}
__device__ __forceinline__ void mma_bf16(float* c, const uint32_t* a, uint32_t b0, uint32_t b1) {
    asm volatile("mma.sync.aligned.m16n8k16.row.col.f32.bf16.bf16.f32 "
                 "{%0,%1,%2,%3}, {%4,%5,%6,%7}, {%8,%9}, {%0,%1,%2,%3};"
                 : "+f"(c[0]), "+f"(c[1]), "+f"(c[2]), "+f"(c[3])
                 : "r"(a[0]), "r"(a[1]), "r"(a[2]), "r"(a[3]), "r"(b0), "r"(b1));
}
__device__ __forceinline__ void cp_async16(uint32_t dst, const void* src) {
    asm volatile("cp.async.cg.shared.global [%0], [%1], 16;" :: "r"(dst), "l"(src) : "memory");
}

// load G chunk rb (64 rows, 64KB) into SMEM buffer boff; 4096 16B units, 4 per thread
__device__ __forceinline__ void load_chunk64(uint32_t sb, uint32_t boff, int rb, int tid) {
    const char* src = (const char*)g_gp + (size_t)rb * 65536 + (size_t)tid * 16;
#pragma unroll
    for (int j = 0; j < 4; j++) {
        int q = tid + j * 1024;
        int r = q >> 6, cu = q & 63;
        uint32_t dst = sb + boff + (uint32_t)r * 1024u + ((uint32_t)(cu ^ (r & 7)) << 4);
        cp_async16(dst, src + j * 16384);
    }
    asm volatile("cp.async.commit_group;" ::: "memory");
}

__global__ __launch_bounds__(NTHREADS, 1)
void lca_main_kernel(const float* __restrict__ u,
                     const float* __restrict__ log_lam,
                     float* __restrict__ out) {
    extern __shared__ char smem[];
    const uint32_t sb = smem_u32(smem);
    uint32_t* flagsm = reinterpret_cast<uint32_t*>(smem + FL_OFF);   // [2][8]
    const int tid  = threadIdx.x;
    const int lane = tid & 31;
    const int warp = tid >> 5;             // 0..31
    const int wm = warp >> 4;              // 0..1  (32-row half)
    const int wn = warp & 15;              // 0..15 (32-col group)
    const int m0 = wm * 32;
    const int n0 = wn * 32;
    const uint32_t un0 = (uint32_t)(n0 >> 3);   // 16B-unit column base (wn*4)
    const int grow0 = blockIdx.x * MT;
    const float lam = expf(log_lam[0]);
    const int r4 = lane >> 2;
    const int c2 = (lane & 3) * 2;

    float acc[2][4][4];                    // [m16 half][n8 frag][quad] = 32 regs

    const uint32_t a_lrow0 = sb + A_OFF + (uint32_t)(m0 + (lane & 15)) * 1024u;
    const uint32_t a_cbs = ((uint32_t)(lane >> 4)) ^ ((uint32_t)(lane & 7));
    const uint32_t b_rowoff = (uint32_t)(lane & 15) * 1024u;
    uint32_t b_pu[2];
#pragma unroll
    for (int p = 0; p < 2; p++)
        b_pu[p] = (((un0 + (uint32_t)(2 * p) + (uint32_t)(lane >> 4)) ^ (uint32_t)(lane & 7)) << 4);

    if (tid < 16) flagsm[tid] = 0u;
    load_chunk64(sb, G_OFF0, 0, tid);      // chunk 0 lands during init epilogue

    // ---- init: v1 = eta*u; a1 = soft(v1) -> SMEM + flags slot0; acc = 0.9*v1 + 0.1*u ----
    {
        bool nzw = false;
#pragma unroll
        for (int fm = 0; fm < 2; fm++)
#pragma unroll
        for (int rh = 0; rh < 2; rh++) {
            int rl = m0 + fm * 16 + rh * 8 + r4;
            const float* urow = u + (size_t)(grow0 + rl) * DIMN;
            uint32_t abase = sb + A_OFF + (uint32_t)rl * 1024u + (uint32_t)(c2 * 2);
            uint32_t sw = (uint32_t)(rl & 7);
#pragma unroll
            for (int ni = 0; ni < 4; ni++) {
                float2 uv = *(const float2*)(urow + n0 + ni * 8 + c2);
                float v0 = ETA * uv.x, v1 = ETA * uv.y;
                float s0 = fabsf(v0) - lam, s1 = fabsf(v1) - lam;
                float a0 = (s0 > 0.0f) ? copysignf(s0, v0) : 0.0f;
                float a1 = (s1 > 0.0f) ? copysignf(s1, v1) : 0.0f;
                nzw |= (a0 != 0.0f) || (a1 != 0.0f);
                __nv_bfloat162 h2 = __floats2bfloat162_rn(a0, a1);
                uint32_t aaddr = abase + (((un0 + (uint32_t)ni) ^ sw) << 4);
                asm volatile("st.shared.b32 [%0], %1;" :: "r"(aaddr), "r"(*(uint32_t*)&h2) : "memory");
                acc[fm][ni][rh * 2 + 0] = fmaf(OMETA, v0, ETA * uv.x);
                acc[fm][ni][rh * 2 + 1] = fmaf(OMETA, v1, ETA * uv.y);
            }
        }
        if (__any_sync(0xFFFFFFFFu, nzw) && lane == 0)
            atomicOr(&flagsm[wn >> 1], 1u);
    }
    // no sync here — first loop pass performs wait_group + __syncthreads

    // ---- 9 iterations x 8 chunks of 64 k-rows; loads overlap MMA (R10 ordering) ----
#pragma unroll 1
    for (int it = 0; it < 9; it++) {
        const int slot = it & 1;
#pragma unroll 1
        for (int kb = 0; kb < 8; kb++) {
            const int c = it * 8 + kb;
            asm volatile("cp.async.wait_group 0;" ::: "memory");
            __syncthreads();   // chunk c visible to all; all MMA(c-1) done
            if (kb == 0 && tid < 8) flagsm[((it + 1) & 1) * 8 + tid] = 0u;

            if (c + 1 < NCH_TOTAL)
                load_chunk64(sb, ((c & 1) ? G_OFF0 : G_OFF1), (kb + 1) & 7, tid);

            if (flagsm[slot * 8 + kb]) {
                const uint32_t buf = sb + ((c & 1) ? G_OFF1 : G_OFF0);
#pragma unroll
                for (int h = 0; h < 4; h++) {
                    const int K = kb * 4 + h;          // global k16 step
                    uint32_t Af[2][4], B0[4], B1[4];
                    uint32_t aoff = (((uint32_t)(K << 1) ^ a_cbs) << 4);
                    ldsm4(Af[0], a_lrow0 + aoff);
                    uint32_t brow = buf + b_rowoff + (uint32_t)(h * 16384);
                    ldsm4t(B0, brow + b_pu[0]);
                    ldsm4(Af[1], a_lrow0 + 16384u + aoff);
                    ldsm4t(B1, brow + b_pu[1]);
#pragma unroll
                    for (int fm = 0; fm < 2; fm++) {
                        mma_bf16(acc[fm][0], Af[fm], B0[0], B0[1]);
                        mma_bf16(acc[fm][1], Af[fm], B0[2], B0[3]);
                        mma_bf16(acc[fm][2], Af[fm], B1[0], B1[1]);
                        mma_bf16(acc[fm][3], Af[fm], B1[2], B1[3]);
                    }
                }
            }
        }
        __syncthreads();   // all MMAs of this iteration done before A-tile rewrite

        if (it < 8) {
            bool nzw = false;
            const int wslot = (it + 1) & 1;
#pragma unroll
            for (int fm = 0; fm < 2; fm++)
#pragma unroll
            for (int rh = 0; rh < 2; rh++) {
                int rl = m0 + fm * 16 + rh * 8 + r4;
                const float* urow = u + (size_t)(grow0 + rl) * DIMN;
                uint32_t abase = sb + A_OFF + (uint32_t)rl * 1024u + (uint32_t)(c2 * 2);
                uint32_t sw = (uint32_t)(rl & 7);
#pragma unroll
                for (int ni = 0; ni < 4; ni++) {
                    float v0 = acc[fm][ni][rh * 2 + 0];
                    float v1 = acc[fm][ni][rh * 2 + 1];
                    float s0 = fabsf(v0) - lam, s1 = fabsf(v1) - lam;
                    float a0 = (s0 > 0.0f) ? copysignf(s0, v0) : 0.0f;
                    float a1 = (s1 > 0.0f) ? copysignf(s1, v1) : 0.0f;
                    nzw |= (a0 != 0.0f) || (a1 != 0.0f);
                    __nv_bfloat162 h2 = __floats2bfloat162_rn(a0, a1);
                    uint32_t aaddr = abase + (((un0 + (uint32_t)ni) ^ sw) << 4);
                    asm volatile("st.shared.b32 [%0], %1;" :: "r"(aaddr), "r"(*(uint32_t*)&h2) : "memory");
                    float2 uv = *(const float2*)(urow + n0 + ni * 8 + c2);
                    acc[fm][ni][rh * 2 + 0] = fmaf(OMETA, v0, ETA * uv.x);
                    acc[fm][ni][rh * 2 + 1] = fmaf(OMETA, v1, ETA * uv.y);
                }
            }
            if (__any_sync(0xFFFFFFFFu, nzw) && lane == 0)
                atomicOr(&flagsm[wslot * 8 + (wn >> 1)], 1u);
            // next iteration's first wait_group+__syncthreads publishes A-tile + flags
        } else {
            // final: a10 = soft(v10) -> out
#pragma unroll
            for (int fm = 0; fm < 2; fm++)
#pragma unroll
            for (int rh = 0; rh < 2; rh++) {
                int rl = m0 + fm * 16 + rh * 8 + r4;
                float* orow = out + (size_t)(grow0 + rl) * DIMN;
#pragma unroll
                for (int ni = 0; ni < 4; ni++) {
                    float v0 = acc[fm][ni][rh * 2 + 0];
                    float v1 = acc[fm][ni][rh * 2 + 1];
                    float s0 = fabsf(v0) - lam, s1 = fabsf(v1) - lam;
                    float2 o;
                    o.x = (s0 > 0.0f) ? copysignf(s0, v0) : 0.0f;
                    o.y = (s1 > 0.0f) ? copysignf(s1, v1) : 0.0f;
                    *(float2*)(orow + n0 + ni * 8 + c2) = o;
                }
            }
        }
    }
}

extern "C" void kernel_launch(void* const* d_in, const int* in_sizes, int n_in,
                              void* d_out, int out_size) {
    const float* u = nullptr;
    const float* G = nullptr;
    const float* ll = nullptr;
    for (int i = 0; i < n_in; i++) {
        if (in_sizes[i] == NROWS * DIMN)      u  = (const float*)d_in[i];
        else if (in_sizes[i] == DIMN * DIMN)  G  = (const float*)d_in[i];
        else                                  ll = (const float*)d_in[i];
    }
    float* out = (float*)d_out;

    lca_prep_kernel<<<DIMN, DIMN>>>(G);

    cudaFuncSetAttribute(lca_main_kernel,
                         cudaFuncAttributeMaxDynamicSharedMemorySize, SMEM_TOTAL);
    lca_main_kernel<<<NCTAS, NTHREADS, SMEM_TOTAL>>>(u, ll, out);
}

// round 14
// speedup vs baseline: 1.0827x; 1.0827x over previous
#include <cuda_runtime.h>
#include <cuda_bf16.h>
#include <cstdint>

#define DIMN 512
#define MT   64
#define NROWS 65536
#define NCTAS (NROWS / MT)        // 1024
#define NTHREADS 512
#define ETA   0.1f
#define OMETA 0.9f
#define NCH_TOTAL (9 * 8)         // 72 chunks of 64 k-rows

// smem: a-tile [64][512] bf16 swizzled (64KB) + 2 G chunk buffers (64KB each) + flags
static constexpr uint32_t A_OFF   = 0;
static constexpr uint32_t G_OFF0  = 65536;
static constexpr uint32_t G_OFF1  = 131072;
static constexpr uint32_t FL_OFF  = 196608;       // flags[2][8]
static constexpr uint32_t SMEM_TOTAL = 196672;

// G' = -eta * (0.5*(G+G^T)) with zero diagonal, bf16, row-major [K=512][N=512]
__device__ __nv_bfloat16 g_gp[DIMN * DIMN];

__global__ void lca_prep_kernel(const float* __restrict__ G) {
    int idx = blockIdx.x * blockDim.x + threadIdx.x;
    int i = idx >> 9, j = idx & 511;
    float v = (i == j) ? 0.0f : -ETA * 0.5f * (G[idx] + G[j * DIMN + i]);
    g_gp[idx] = __float2bfloat16(v);
}

__device__ __forceinline__ uint32_t smem_u32(const void* p) {
    uint32_t a;
    asm("{ .reg .u64 t; cvta.to.shared.u64 t, %1; cvt.u32.u64 %0, t; }" : "=r"(a) : "l"(p));
    return a;
}
__device__ __forceinline__ void ldsm4(uint32_t* r, uint32_t addr) {
    asm volatile("ldmatrix.sync.aligned.m8n8.x4.shared.b16 {%0,%1,%2,%3}, [%4];"
                 : "=r"(r[0]), "=r"(r[1]), "=r"(r[2]), "=r"(r[3]) : "r"(addr));
}
__device__ __forceinline__ void ldsm4t(uint32_t* r, uint32_t addr) {
    asm volatile("ldmatrix.sync.aligned.m8n8.x4.trans.shared.b16 {%0,%1,%2,%3}, [%4];"
                 : "=r"(r[0]), "=r"(r[1]), "=r"(r[2]), "=r"(r[3]) : "r"(addr));
}
__device__ __forceinline__ void mma_bf16(float* c, const uint32_t* a, uint32_t b0, uint32_t b1) {
    asm volatile("mma.sync.aligned.m16n8k16.row.col.f32.bf16.bf16.f32 "
                 "{%0,%1,%2,%3}, {%4,%5,%6,%7}, {%8,%9}, {%0,%1,%2,%3};"
                 : "+f"(c[0]), "+f"(c[1]), "+f"(c[2]), "+f"(c[3])
                 : "r"(a[0]), "r"(a[1]), "r"(a[2]), "r"(a[3]), "r"(b0), "r"(b1));
}
__device__ __forceinline__ void cp_async16(uint32_t dst, const void* src) {
    asm volatile("cp.async.cg.shared.global [%0], [%1], 16;" :: "r"(dst), "l"(src) : "memory");
}

// load G chunk rb (64 rows, 64KB) into SMEM buffer boff; 4096 16B units, 8 per thread
__device__ __forceinline__ void load_chunk64(uint32_t sb, uint32_t boff, int rb, int tid) {
    const char* src = (const char*)g_gp + (size_t)rb * 65536 + (size_t)tid * 16;
#pragma unroll
    for (int j = 0; j < 8; j++) {
        int q = tid + j * 512;
        int r = q >> 6, cu = q & 63;
        uint32_t dst = sb + boff + (uint32_t)r * 1024u + ((uint32_t)(cu ^ (r & 7)) << 4);
        cp_async16(dst, src + j * 8192);
    }
    asm volatile("cp.async.commit_group;" ::: "memory");
}

__global__ __launch_bounds__(NTHREADS, 1)
void lca_main_kernel(const float* __restrict__ u,
                     const float* __restrict__ log_lam,
                     float* __restrict__ out) {
    extern __shared__ char smem[];
    const uint32_t sb = smem_u32(smem);
    uint32_t* flagsm = reinterpret_cast<uint32_t*>(smem + FL_OFF);   // [2][8]
    const int tid  = threadIdx.x;
    const int lane = tid & 31;
    const int warp = tid >> 5;
    const int wm = warp >> 3;              // 0..1
    const int wn = warp & 7;               // 0..7
    const int m0 = wm * 32;
    const int n0 = wn * 64;
    const uint32_t un0 = (uint32_t)(n0 >> 3);
    const int grow0 = blockIdx.x * MT;
    const float lam = expf(log_lam[0]);
    const int r4 = lane >> 2;
    const int c2 = (lane & 3) * 2;

    float acc[2][8][4];                    // 64 regs

    const uint32_t a_lrow0 = sb + A_OFF + (uint32_t)(m0 + (lane & 15)) * 1024u;
    const uint32_t a_lrow1 = a_lrow0 + 16u * 1024u;
    const uint32_t a_cbs = ((uint32_t)(lane >> 4)) ^ ((uint32_t)(lane & 7));
    const uint32_t b_rowoff = (uint32_t)(lane & 15) * 1024u;
    uint32_t b_pu[4];
#pragma unroll
    for (int p = 0; p < 4; p++)
        b_pu[p] = (((un0 + (uint32_t)(2 * p) + (uint32_t)(lane >> 4)) ^ (uint32_t)(lane & 7)) << 4);

    if (tid < 16) flagsm[tid] = 0u;
    load_chunk64(sb, G_OFF0, 0, tid);     // chunk 0 lands during init epilogue

    // ---- init: v1 = eta*u; a1 = soft(v1) -> SMEM + flags slot0; acc = 0.9*v1 + 0.1*u ----
    {
        bool nzw = false;
#pragma unroll
        for (int fm = 0; fm < 2; fm++)
#pragma unroll
        for (int rh = 0; rh < 2; rh++) {
            int rl = m0 + fm * 16 + rh * 8 + r4;
            const float* urow = u + (size_t)(grow0 + rl) * DIMN;
            uint32_t abase = sb + A_OFF + (uint32_t)rl * 1024u + (uint32_t)(c2 * 2);
            uint32_t sw = (uint32_t)(rl & 7);
#pragma unroll
            for (int ni = 0; ni < 8; ni++) {
                float2 uv = *(const float2*)(urow + n0 + ni * 8 + c2);
                float v0 = ETA * uv.x, v1 = ETA * uv.y;
                float s0 = fabsf(v0) - lam, s1 = fabsf(v1) - lam;
                float a0 = (s0 > 0.0f) ? copysignf(s0, v0) : 0.0f;
                float a1 = (s1 > 0.0f) ? copysignf(s1, v1) : 0.0f;
                nzw |= (a0 != 0.0f) || (a1 != 0.0f);
                __nv_bfloat162 h2 = __floats2bfloat162_rn(a0, a1);
                uint32_t aaddr = abase + (((un0 + (uint32_t)ni) ^ sw) << 4);
                asm volatile("st.shared.b32 [%0], %1;" :: "r"(aaddr), "r"(*(uint32_t*)&h2) : "memory");
                acc[fm][ni][rh * 2 + 0] = fmaf(OMETA, v0, ETA * uv.x);
                acc[fm][ni][rh * 2 + 1] = fmaf(OMETA, v1, ETA * uv.y);
            }
        }
        if (__any_sync(0xFFFFFFFFu, nzw) && lane == 0) atomicOr(&flagsm[wn], 1u);
    }
    // no sync here — first loop pass performs wait_group + __syncthreads

    // ---- 9 iterations x 8 chunks of 64 k-rows; half-step (k16 x n32) software pipeline ----
#pragma unroll 1
    for (int it = 0; it < 9; it++) {
        const int slot = it & 1;
#pragma unroll 1
        for (int kb = 0; kb < 8; kb++) {
            const int c = it * 8 + kb;
            asm volatile("cp.async.wait_group 0;" ::: "memory");
            __syncthreads();   // chunk c visible; all MMA(c-1) done
            if (kb == 0 && tid < 8) flagsm[((it + 1) & 1) * 8 + tid] = 0u;

            // issue load of chunk c+1 into other buffer (readers MMA(c-1) fenced above)
            if (c + 1 < NCH_TOTAL)
                load_chunk64(sb, ((c & 1) ? G_OFF0 : G_OFF1), (kb + 1) & 7, tid);

            if (flagsm[slot * 8 + kb]) {
                const uint32_t buf = sb + ((c & 1) ? G_OFF1 : G_OFF0);
                uint32_t Af[2][8];   // A frags, double-buffered per k16 step (16 regs)
                uint32_t Bh[2][8];   // B frags, double-buffered per half-step (16 regs)
                {   // preload: A step 0, B (step 0, half 0)
                    uint32_t aoff = (((uint32_t)(kb << 3) ^ a_cbs) << 4);
                    ldsm4(&Af[0][0], a_lrow0 + aoff);
                    ldsm4(&Af[0][4], a_lrow1 + aoff);
                    uint32_t brow = buf + b_rowoff;
                    ldsm4t(&Bh[0][0], brow + b_pu[0]);
                    ldsm4t(&Bh[0][4], brow + b_pu[1]);
                }
#pragma unroll
                for (int q = 0; q < 8; q++) {          // 4 k16 steps x 2 n32 halves
                    const int h  = q >> 1;             // k16 step 0..3
                    const int hf = q & 1;              // n32 half
                    const int bcur = q & 1, bnxt = bcur ^ 1;
                    const int acur = h & 1;
                    if (q < 7) {                        // prefetch next half (and next step's A)
                        const int qn = q + 1, hn = qn >> 1, hfn = qn & 1;
                        uint32_t brow = buf + b_rowoff + (uint32_t)(hn * 16384);
                        ldsm4t(&Bh[bnxt][0], brow + b_pu[2 * hfn + 0]);
                        ldsm4t(&Bh[bnxt][4], brow + b_pu[2 * hfn + 1]);
                        if (hfn == 0) {                 // new k16 step begins at qn
                            uint32_t aoff = (((uint32_t)((kb * 4 + hn) << 1) ^ a_cbs) << 4);
                            ldsm4(&Af[hn & 1][0], a_lrow0 + aoff);
                            ldsm4(&Af[hn & 1][4], a_lrow1 + aoff);
                        }
                    }
                    // 8 HMMA on (step h, half hf): acc ni = hf*4 .. hf*4+3
                    const int nb = hf * 4;
                    mma_bf16(acc[0][nb + 0], &Af[acur][0], Bh[bcur][0], Bh[bcur][1]);
                    mma_bf16(acc[0][nb + 1], &Af[acur][0], Bh[bcur][2], Bh[bcur][3]);
                    mma_bf16(acc[0][nb + 2], &Af[acur][0], Bh[bcur][4], Bh[bcur][5]);
                    mma_bf16(acc[0][nb + 3], &Af[acur][0], Bh[bcur][6], Bh[bcur][7]);
                    mma_bf16(acc[1][nb + 0], &Af[acur][4], Bh[bcur][0], Bh[bcur][1]);
                    mma_bf16(acc[1][nb + 1], &Af[acur][4], Bh[bcur][2], Bh[bcur][3]);
                    mma_bf16(acc[1][nb + 2], &Af[acur][4], Bh[bcur][4], Bh[bcur][5]);
                    mma_bf16(acc[1][nb + 3], &Af[acur][4], Bh[bcur][6], Bh[bcur][7]);
                }
            }
        }
        __syncthreads();   // all MMAs of this iteration done before A-tile rewrite

        if (it < 8) {
            bool nzw = false;
            const int wslot = (it + 1) & 1;
#pragma unroll
            for (int fm = 0; fm < 2; fm++)
#pragma unroll
            for (int rh = 0; rh < 2; rh++) {
                int rl = m0 + fm * 16 + rh * 8 + r4;
                const float* urow = u + (size_t)(grow0 + rl) * DIMN;
                uint32_t abase = sb + A_OFF + (uint32_t)rl * 1024u + (uint32_t)(c2 * 2);
                uint32_t sw = (uint32_t)(rl & 7);
#pragma unroll
                for (int ni = 0; ni < 8; ni++) {
                    float v0 = acc[fm][ni][rh * 2 + 0];
                    float v1 = acc[fm][ni][rh * 2 + 1];
                    float s0 = fabsf(v0) - lam, s1 = fabsf(v1) - lam;
                    float a0 = (s0 > 0.0f) ? copysignf(s0, v0) : 0.0f;
                    float a1 = (s1 > 0.0f) ? copysignf(s1, v1) : 0.0f;
                    nzw |= (a0 != 0.0f) || (a1 != 0.0f);
                    __nv_bfloat162 h2 = __floats2bfloat162_rn(a0, a1);
                    uint32_t aaddr = abase + (((un0 + (uint32_t)ni) ^ sw) << 4);
                    asm volatile("st.shared.b32 [%0], %1;" :: "r"(aaddr), "r"(*(uint32_t*)&h2) : "memory");
                    float2 uv = *(const float2*)(urow + n0 + ni * 8 + c2);
                    acc[fm][ni][rh * 2 + 0] = fmaf(OMETA, v0, ETA * uv.x);
                    acc[fm][ni][rh * 2 + 1] = fmaf(OMETA, v1, ETA * uv.y);
                }
            }
            if (__any_sync(0xFFFFFFFFu, nzw) && lane == 0)
                atomicOr(&flagsm[wslot * 8 + wn], 1u);
            // next iteration's first wait_group + __syncthreads publishes A-tile + flags
        } else {
            // final: a10 = soft(v10) -> out
#pragma unroll
            for (int fm = 0; fm < 2; fm++)
#pragma unroll
            for (int rh = 0; rh < 2; rh++) {
                int rl = m0 + fm * 16 + rh * 8 + r4;
                float* orow = out + (size_t)(grow0 + rl) * DIMN;
#pragma unroll
                for (int ni = 0; ni < 8; ni++) {
                    float v0 = acc[fm][ni][rh * 2 + 0];
                    float v1 = acc[fm][ni][rh * 2 + 1];
                    float s0 = fabsf(v0) - lam, s1 = fabsf(v1) - lam;
                    float2 o;
                    o.x = (s0 > 0.0f) ? copysignf(s0, v0) : 0.0f;
                    o.y = (s1 > 0.0f) ? copysignf(s1, v1) : 0.0f;
                    *(float2*)(orow + n0 + ni * 8 + c2) = o;
                }
            }
        }
    }
}

extern "C" void kernel_launch(void* const* d_in, const int* in_sizes, int n_in,
                              void* d_out, int out_size) {
    const float* u = nullptr;
    const float* G = nullptr;
    const float* ll = nullptr;
    for (int i = 0; i < n_in; i++) {
        if (in_sizes[i] == NROWS * DIMN)      u  = (const float*)d_in[i];
        else if (in_sizes[i] == DIMN * DIMN)  G  = (const float*)d_in[i];
        else                                  ll = (const float*)d_in[i];
    }
    float* out = (float*)d_out;

    lca_prep_kernel<<<DIMN, DIMN>>>(G);

    cudaFuncSetAttribute(lca_main_kernel,
                         cudaFuncAttributeMaxDynamicSharedMemorySize, SMEM_TOTAL);
    lca_main_kernel<<<NCTAS, NTHREADS, SMEM_TOTAL>>>(u, ll, out);
}

// round 15
// speedup vs baseline: 1.3502x; 1.2472x over previous
#include <cuda_runtime.h>
#include <cuda_bf16.h>
#include <cstdint>

#define DIMN 512
#define MT   64
#define NROWS 65536
#define NCTAS (NROWS / MT)        // 1024
#define NTHREADS 512
#define ETA   0.1f
#define OMETA 0.9f

// SMEM: A-tile [64][512] bf16 swizzled (64KB) + flags[2][8] + any[2]
static constexpr uint32_t A_OFF  = 0;
static constexpr uint32_t FL_OFF = 65536;
static constexpr uint32_t SMEM_TOTAL = 65536 + 128;

// B-fragment image of G' = -eta*0.5*(G+G^T) (diag 0), bf16, laid out exactly as
// mma.sync.m16n8k16 .col B fragments:
//   u32 index = ((s*16 + wc)*32 + lane)*8 + g*2 + r
//   s = k16 step (0..31), wc = warp col-group (0..15, n = wc*32..+31),
//   g = n8 group (0..3), r = reg (0: k rows 0..7 half, 1: k rows 8..15 half)
//   reg r holds {G'[k][n], G'[k+1][n]} with k = s*16 + (lane&3)*2 + r*8,
//   n = wc*32 + g*8 + (lane>>2);  low bf16 = even k.
__device__ uint32_t g_bfrag[32 * 16 * 32 * 8];   // 512KB

__global__ void lca_prep_kernel(const float* __restrict__ G) {
    int idx = blockIdx.x * blockDim.x + threadIdx.x;   // 65536
    int g  = idx & 3;
    int l  = (idx >> 2) & 31;
    int wc = (idx >> 7) & 15;
    int s  = idx >> 11;
    int n  = wc * 32 + g * 8 + (l >> 2);
    int k0 = s * 16 + (l & 3) * 2;
    float v00 = (k0     == n) ? 0.0f : -0.05f * (G[(k0    ) * DIMN + n] + G[n * DIMN + (k0    )]);
    float v01 = (k0 + 1 == n) ? 0.0f : -0.05f * (G[(k0 + 1) * DIMN + n] + G[n * DIMN + (k0 + 1)]);
    float v10 = (k0 + 8 == n) ? 0.0f : -0.05f * (G[(k0 + 8) * DIMN + n] + G[n * DIMN + (k0 + 8)]);
    float v11 = (k0 + 9 == n) ? 0.0f : -0.05f * (G[(k0 + 9) * DIMN + n] + G[n * DIMN + (k0 + 9)]);
    __nv_bfloat162 p0 = __floats2bfloat162_rn(v00, v01);
    __nv_bfloat162 p1 = __floats2bfloat162_rn(v10, v11);
    uint32_t* dst = g_bfrag + ((((size_t)s * 16 + wc) * 32 + l) * 8 + g * 2);
    dst[0] = *reinterpret_cast<uint32_t*>(&p0);
    dst[1] = *reinterpret_cast<uint32_t*>(&p1);
}

__device__ __forceinline__ uint32_t smem_u32(const void* p) {
    uint32_t a;
    asm("{ .reg .u64 t; cvta.to.shared.u64 t, %1; cvt.u32.u64 %0, t; }" : "=r"(a) : "l"(p));
    return a;
}
__device__ __forceinline__ void ldsm4(uint32_t* r, uint32_t addr) {
    asm volatile("ldmatrix.sync.aligned.m8n8.x4.shared.b16 {%0,%1,%2,%3}, [%4];"
                 : "=r"(r[0]), "=r"(r[1]), "=r"(r[2]), "=r"(r[3]) : "r"(addr));
}
__device__ __forceinline__ void mma_bf16(float* c, const uint32_t* a, uint32_t b0, uint32_t b1) {
    asm volatile("mma.sync.aligned.m16n8k16.row.col.f32.bf16.bf16.f32 "
                 "{%0,%1,%2,%3}, {%4,%5,%6,%7}, {%8,%9}, {%0,%1,%2,%3};"
                 : "+f"(c[0]), "+f"(c[1]), "+f"(c[2]), "+f"(c[3])
                 : "r"(a[0]), "r"(a[1]), "r"(a[2]), "r"(a[3]), "r"(b0), "r"(b1));
}

__global__ __launch_bounds__(NTHREADS, 1)
void lca_main_kernel(const float* __restrict__ u,
                     const float* __restrict__ log_lam,
                     float* __restrict__ out) {
    extern __shared__ char smem[];
    const uint32_t sb = smem_u32(smem);
    uint32_t* flagsm = reinterpret_cast<uint32_t*>(smem + FL_OFF);   // [0..15] flags, [16..17] any
    const int tid  = threadIdx.x;
    const int lane = tid & 31;
    const int wc   = tid >> 5;             // warp 0..15 owns n cols wc*32..+31, ALL 64 rows
    const int n0   = wc * 32;
    const int grow0 = blockIdx.x * MT;
    const float lam = expf(log_lam[0]);
    const int r4 = lane >> 2;
    const int c2 = (lane & 3) * 2;

    float acc[4][4][4];                    // [m16 grp][n8 grp][quad] = 64 regs

    // A-operand ldsm addressing (proven layout): row-group q at a_l0 + q*16384
    const uint32_t a_l0 = sb + A_OFF + (uint32_t)(lane & 15) * 1024u;
    const uint32_t a_cbs = ((uint32_t)(lane >> 4)) ^ ((uint32_t)(lane & 7));
    // B-frag global base for this (warp, lane)
    const char* bwbase = (const char*)g_bfrag + ((size_t)wc * 32 + (size_t)lane) * 32;

    // clear flags slot0 + any[0] before any OR
    if (tid < 8) flagsm[tid] = 0u;
    if (tid == 8) flagsm[16] = 0u;
    __syncthreads();

    // ---- init: v1 = eta*u; a1 = soft(v1) -> SMEM + flags slot0; acc = 0.9*v1 + 0.1*u ----
    {
        bool nzw = false;
#pragma unroll
        for (int fm = 0; fm < 4; fm++)
#pragma unroll
        for (int rh = 0; rh < 2; rh++) {
            int rl = fm * 16 + rh * 8 + r4;
            const float* urow = u + (size_t)(grow0 + rl) * DIMN;
            uint32_t abase = sb + A_OFF + (uint32_t)rl * 1024u + (uint32_t)(c2 * 2);
            uint32_t sw = (uint32_t)(rl & 7);
#pragma unroll
            for (int ni = 0; ni < 4; ni++) {
                float2 uv = *(const float2*)(urow + n0 + ni * 8 + c2);
                float v0 = ETA * uv.x, v1 = ETA * uv.y;
                float s0 = fabsf(v0) - lam, s1 = fabsf(v1) - lam;
                float a0 = (s0 > 0.0f) ? copysignf(s0, v0) : 0.0f;
                float a1 = (s1 > 0.0f) ? copysignf(s1, v1) : 0.0f;
                nzw |= (a0 != 0.0f) || (a1 != 0.0f);
                __nv_bfloat162 h2 = __floats2bfloat162_rn(a0, a1);
                uint32_t unit = (uint32_t)(wc * 4 + ni);
                uint32_t aaddr = abase + ((unit ^ sw) << 4);
                asm volatile("st.shared.b32 [%0], %1;" :: "r"(aaddr), "r"(*(uint32_t*)&h2) : "memory");
                acc[fm][ni][rh * 2 + 0] = fmaf(OMETA, v0, ETA * uv.x);
                acc[fm][ni][rh * 2 + 1] = fmaf(OMETA, v1, ETA * uv.y);
            }
        }
        if (__any_sync(0xFFFFFFFFu, nzw) && lane == 0) {
            atomicOr(&flagsm[wc >> 1], 1u);
            atomicOr(&flagsm[16], 1u);
        }
    }
    __syncthreads();   // A-tile + flags slot0 visible

    // ---- 9 iterations; NO barriers inside the k loop (B never touches SMEM) ----
#pragma unroll 1
    for (int it = 0; it < 9; it++) {
        const int slot = it & 1;
        const int wslot = slot ^ 1;
        // clear next-slot flags (ordered vs. readers by prev end-barrier, vs. writers by mid-barrier)
        if (it < 8) {
            if (tid < 8) flagsm[wslot * 8 + tid] = 0u;
            if (tid == 8) flagsm[16 + wslot] = 0u;
        }

        if (flagsm[16 + slot]) {
#pragma unroll 1
            for (int kb = 0; kb < 8; kb++) {
                if (!flagsm[slot * 8 + kb]) continue;
                const int s0 = kb * 4;
                const uint4* bp0 = reinterpret_cast<const uint4*>(bwbase + (size_t)s0 * 16384);
                uint4 Bx = __ldg(bp0);
                uint4 By = __ldg(bp0 + 1);
#pragma unroll
                for (int h = 0; h < 4; h++) {
                    const int s = s0 + h;
                    uint32_t aoff = (((uint32_t)(s << 1) ^ a_cbs) << 4);
                    uint32_t Af[4][4];
                    ldsm4(Af[0], a_l0 + aoff);
                    ldsm4(Af[1], a_l0 + 16384u + aoff);
                    ldsm4(Af[2], a_l0 + 32768u + aoff);
                    ldsm4(Af[3], a_l0 + 49152u + aoff);
                    uint4 Bxn, Byn;
                    if (h < 3) {
                        const uint4* bn = reinterpret_cast<const uint4*>(bwbase + (size_t)(s + 1) * 16384);
                        Bxn = __ldg(bn);
                        Byn = __ldg(bn + 1);
                    }
#pragma unroll
                    for (int q = 0; q < 4; q++) {
                        mma_bf16(acc[q][0], Af[q], Bx.x, Bx.y);
                        mma_bf16(acc[q][1], Af[q], Bx.z, Bx.w);
                        mma_bf16(acc[q][2], Af[q], By.x, By.y);
                        mma_bf16(acc[q][3], Af[q], By.z, By.w);
                    }
                    if (h < 3) { Bx = Bxn; By = Byn; }
                }
            }
        }
        __syncthreads();   // all warps' MMAs done before A-tile rewrite (mid-barrier)

        if (it < 8) {
            bool nzw = false;
#pragma unroll
            for (int fm = 0; fm < 4; fm++)
#pragma unroll
            for (int rh = 0; rh < 2; rh++) {
                int rl = fm * 16 + rh * 8 + r4;
                const float* urow = u + (size_t)(grow0 + rl) * DIMN;
                uint32_t abase = sb + A_OFF + (uint32_t)rl * 1024u + (uint32_t)(c2 * 2);
                uint32_t sw = (uint32_t)(rl & 7);
#pragma unroll
                for (int ni = 0; ni < 4; ni++) {
                    float v0 = acc[fm][ni][rh * 2 + 0];
                    float v1 = acc[fm][ni][rh * 2 + 1];
                    float s0 = fabsf(v0) - lam, s1 = fabsf(v1) - lam;
                    float a0 = (s0 > 0.0f) ? copysignf(s0, v0) : 0.0f;
                    float a1 = (s1 > 0.0f) ? copysignf(s1, v1) : 0.0f;
                    nzw |= (a0 != 0.0f) || (a1 != 0.0f);
                    __nv_bfloat162 h2 = __floats2bfloat162_rn(a0, a1);
                    uint32_t unit = (uint32_t)(wc * 4 + ni);
                    uint32_t aaddr = abase + ((unit ^ sw) << 4);
                    asm volatile("st.shared.b32 [%0], %1;" :: "r"(aaddr), "r"(*(uint32_t*)&h2) : "memory");
                    float2 uv = *(const float2*)(urow + n0 + ni * 8 + c2);
                    acc[fm][ni][rh * 2 + 0] = fmaf(OMETA, v0, ETA * uv.x);
                    acc[fm][ni][rh * 2 + 1] = fmaf(OMETA, v1, ETA * uv.y);
                }
            }
            if (__any_sync(0xFFFFFFFFu, nzw) && lane == 0) {
                atomicOr(&flagsm[wslot * 8 + (wc >> 1)], 1u);
                atomicOr(&flagsm[16 + wslot], 1u);
            }
            __syncthreads();   // end-barrier: a_{t+1} + flags visible
        } else {
            // final: a10 = soft(v10) -> out
#pragma unroll
            for (int fm = 0; fm < 4; fm++)
#pragma unroll
            for (int rh = 0; rh < 2; rh++) {
                int rl = fm * 16 + rh * 8 + r4;
                float* orow = out + (size_t)(grow0 + rl) * DIMN;
#pragma unroll
                for (int ni = 0; ni < 4; ni++) {
                    float v0 = acc[fm][ni][rh * 2 + 0];
                    float v1 = acc[fm][ni][rh * 2 + 1];
                    float s0 = fabsf(v0) - lam, s1 = fabsf(v1) - lam;
                    float2 o;
                    o.x = (s0 > 0.0f) ? copysignf(s0, v0) : 0.0f;
                    o.y = (s1 > 0.0f) ? copysignf(s1, v1) : 0.0f;
                    *(float2*)(orow + n0 + ni * 8 + c2) = o;
                }
            }
        }
    }
}

extern "C" void kernel_launch(void* const* d_in, const int* in_sizes, int n_in,
                              void* d_out, int out_size) {
    const float* u = nullptr;
    const float* G = nullptr;
    const float* ll = nullptr;
    for (int i = 0; i < n_in; i++) {
        if (in_sizes[i] == NROWS * DIMN)      u  = (const float*)d_in[i];
        else if (in_sizes[i] == DIMN * DIMN)  G  = (const float*)d_in[i];
        else                                  ll = (const float*)d_in[i];
    }
    float* out = (float*)d_out;

    lca_prep_kernel<<<128, 512>>>(G);

    cudaFuncSetAttribute(lca_main_kernel,
                         cudaFuncAttributeMaxDynamicSharedMemorySize, SMEM_TOTAL);
    lca_main_kernel<<<NCTAS, NTHREADS, SMEM_TOTAL>>>(u, ll, out);
}